// round 1
// baseline (speedup 1.0000x reference)
#include <cuda_runtime.h>
#include <cuda_bf16.h>
#include <cstdint>
#include <cstddef>

// Problem shape (fixed by setup_inputs): B=4, S=2048, D=2048, P=int(2048*1.333)=2729
#define BSD 8192   // B*S rows
#define DD  2048   // model dim
#define PD  2729   // projection dim
#define PPD 2752   // P padded to multiple of 32 (for K-tiling & float4 alignment)
#define BB  4
#define SS  2048

// ---------------- scratch (device globals: the sanctioned no-alloc path) ----
__device__ float g_xn [(size_t)BSD * DD];    // rmsnorm(x)
__device__ float g_gi [(size_t)BSD * PPD];   // sigmoid(softcap(xn@Wi^T))
__device__ float g_gf [(size_t)BSD * PPD];
__device__ float g_go [(size_t)BSD * PPD];
__device__ float g_gc [(size_t)BSD * PPD];   // tanh(xn@Wc^T)
__device__ float g_act[(size_t)BSD * PPD];   // scan output o*tanh(h); pad cols stay 0
__device__ float g_wout[(size_t)DD * PPD];   // Wout padded to PPD, pad zeroed

// ---------------- helpers ---------------------------------------------------
__device__ __forceinline__ void cp16(uint32_t dst, const float* src, int nbytes) {
    asm volatile("cp.async.cg.shared.global [%0], [%1], 16, %2;\n"
                 :: "r"(dst), "l"(src), "r"(nbytes));
}
__device__ __forceinline__ void cp_commit() { asm volatile("cp.async.commit_group;\n"); }
__device__ __forceinline__ void cp_wait1()  { asm volatile("cp.async.wait_group 1;\n" ::: "memory"); }

// m16n8k8 tf32 TN mma (A row-major frag, B col-major frag), fp32 accum
__device__ __forceinline__ void mma8(float* c, const float* a, const float* b) {
    const uint32_t* ai = reinterpret_cast<const uint32_t*>(a);
    const uint32_t* bi = reinterpret_cast<const uint32_t*>(b);
    asm volatile(
        "mma.sync.aligned.m16n8k8.row.col.f32.tf32.tf32.f32 "
        "{%0,%1,%2,%3}, {%4,%5,%6,%7}, {%8,%9}, {%0,%1,%2,%3};\n"
        : "+f"(c[0]), "+f"(c[1]), "+f"(c[2]), "+f"(c[3])
        : "r"(ai[0]), "r"(ai[1]), "r"(ai[2]), "r"(ai[3]),
          "r"(bi[0]), "r"(bi[1]));
}

__device__ __forceinline__ float gate_act(float z, bool tanhOnly) {
    if (tanhOnly) return tanhf(z);
    float t = 15.0f * tanhf(z * (1.0f / 15.0f));   // soft cap
    return 1.0f / (1.0f + expf(-t));               // sigmoid
}

// ---------------- rmsnorm ---------------------------------------------------
__global__ void rmsnorm_kernel(const float* __restrict__ x, const float* __restrict__ w) {
    int row = blockIdx.x;
    int t = threadIdx.x;  // 256 threads, 2048 floats/row -> 2 float4 each
    const float4* xr = reinterpret_cast<const float4*>(x + (size_t)row * DD);
    float4 v0 = xr[t];
    float4 v1 = xr[t + 256];
    float ss = v0.x*v0.x + v0.y*v0.y + v0.z*v0.z + v0.w*v0.w
             + v1.x*v1.x + v1.y*v1.y + v1.z*v1.z + v1.w*v1.w;
    #pragma unroll
    for (int o = 16; o > 0; o >>= 1) ss += __shfl_xor_sync(0xffffffffu, ss, o);
    __shared__ float red[8];
    if ((t & 31) == 0) red[t >> 5] = ss;
    __syncthreads();
    float tot = red[0]+red[1]+red[2]+red[3]+red[4]+red[5]+red[6]+red[7];
    float r = rsqrtf(tot * (1.0f / DD) + 1e-6f);
    const float4* wr = reinterpret_cast<const float4*>(w);
    float4 w0 = wr[t], w1 = wr[t + 256];
    float4 o0 = make_float4(v0.x*r*w0.x, v0.y*r*w0.y, v0.z*r*w0.z, v0.w*r*w0.w);
    float4 o1 = make_float4(v1.x*r*w1.x, v1.y*r*w1.y, v1.z*r*w1.z, v1.w*r*w1.w);
    float4* dst = reinterpret_cast<float4*>(g_xn + (size_t)row * DD);
    dst[t] = o0;
    dst[t + 256] = o1;
}

// ---------------- Wout pad-copy (D x P -> D x PPD, pad zeroed) --------------
__global__ void pad_wout_kernel(const float* __restrict__ wout) {
    size_t i = (size_t)blockIdx.x * blockDim.x + threadIdx.x;
    if (i >= (size_t)DD * PPD) return;
    int d = (int)(i / PPD);
    int p = (int)(i % PPD);
    g_wout[i] = (p < PD) ? wout[(size_t)d * PD + p] : 0.0f;
}

// ---------------- tf32 TN GEMM: C[M,N] = A[M,K] * B[N,K]^T ------------------
// MODE 0: A=g_xn (lda=DD, K=DD), B=W[blockIdx.z] (ldb=DD), N=PD,
//         epilogue = gate activation, store planar into g_gi/gf/go/gc (ldc=PPD)
// MODE 1: A=g_act (lda=PPD, K=PPD incl. zero pad), B=g_wout (ldb=PPD), N=DD,
//         epilogue = + residual x, store to d_out
template<int MODE>
__global__ __launch_bounds__(256) void gemm_tn(
    const float* __restrict__ W0, const float* __restrict__ W1,
    const float* __restrict__ W2, const float* __restrict__ W3,
    const float* __restrict__ resid, float* __restrict__ outp,
    int N, int K, int lda, int ldb)
{
    constexpr int BM = 128, BN = 128, BK = 32, LDSK = BK + 4, STAGES = 3;
    constexpr int STAGE_F = BM * LDSK;
    extern __shared__ float smem[];
    float* As = smem;
    float* Bs = smem + STAGES * STAGE_F;

    const float* A;
    const float* Bw;
    float* C;
    bool actTanh = false;
    if (MODE == 0) {
        A = g_xn;
        int z = blockIdx.z;
        Bw = (z == 0) ? W0 : (z == 1) ? W1 : (z == 2) ? W2 : W3;
        C  = (z == 0) ? g_gi : (z == 1) ? g_gf : (z == 2) ? g_go : g_gc;
        actTanh = (z == 3);
    } else {
        A = g_act; Bw = g_wout; C = outp;
    }

    const int tid = threadIdx.x;
    const int m0 = blockIdx.y * BM;
    const int n0 = blockIdx.x * BN;

    auto issue_stage = [&](int stage, int kt) {
        const int k0 = kt * BK;
        float* as = As + stage * STAGE_F;
        float* bs = Bs + stage * STAGE_F;
        #pragma unroll
        for (int i = 0; i < 4; ++i) {
            int lin = tid + i * 256;
            int r = lin >> 3;          // 0..127
            int c = (lin & 7) << 2;    // 0,4,...,28
            const float* srcA = A + (size_t)(m0 + r) * lda + (k0 + c);
            cp16((uint32_t)__cvta_generic_to_shared(as + r * LDSK + c), srcA, 16);
            int nr = n0 + r;
            int ok = (nr < N);
            const float* srcB = Bw + (size_t)(ok ? nr : 0) * ldb + (k0 + c);
            cp16((uint32_t)__cvta_generic_to_shared(bs + r * LDSK + c), srcB, ok ? 16 : 0);
        }
        cp_commit();
    };

    const int lane = tid & 31;
    const int warp = tid >> 5;
    const int wm = warp & 3;        // 4 warps along M (32 rows each)
    const int wn = warp >> 2;       // 2 warps along N (64 cols each)
    const int qr = lane >> 2;       // groupID
    const int qc = lane & 3;        // threadID_in_group

    float acc[2][8][4];
    #pragma unroll
    for (int im = 0; im < 2; ++im)
        #pragma unroll
        for (int in = 0; in < 8; ++in)
            #pragma unroll
            for (int j = 0; j < 4; ++j) acc[im][in][j] = 0.0f;

    const int KT = K / BK;
    issue_stage(0, 0);
    issue_stage(1, 1);
    cp_wait1();
    __syncthreads();

    for (int kt = 0; kt < KT; ++kt) {
        int s = kt % 3;
        if (kt + 2 < KT) issue_stage((kt + 2) % 3, kt + 2);
        else cp_commit();

        const float* as = As + s * STAGE_F + (wm * 32 + qr) * LDSK + qc;
        const float* bs = Bs + s * STAGE_F + (wn * 64 + qr) * LDSK + qc;

        #pragma unroll
        for (int ks = 0; ks < 4; ++ks) {
            float ra[2][4];
            float rb[8][2];
            #pragma unroll
            for (int im = 0; im < 2; ++im) {
                const float* p = as + im * 16 * LDSK + ks * 8;
                ra[im][0] = p[0];
                ra[im][1] = p[8 * LDSK];
                ra[im][2] = p[4];
                ra[im][3] = p[8 * LDSK + 4];
            }
            #pragma unroll
            for (int in = 0; in < 8; ++in) {
                const float* p = bs + in * 8 * LDSK + ks * 8;
                rb[in][0] = p[0];
                rb[in][1] = p[4];
            }
            #pragma unroll
            for (int im = 0; im < 2; ++im)
                #pragma unroll
                for (int in = 0; in < 8; ++in)
                    mma8(acc[im][in], ra[im], rb[in]);
        }
        cp_wait1();
        __syncthreads();
    }

    // epilogue
    #pragma unroll
    for (int im = 0; im < 2; ++im) {
        int r = m0 + wm * 32 + im * 16 + qr;
        #pragma unroll
        for (int in = 0; in < 8; ++in) {
            int c = n0 + wn * 64 + in * 8 + qc * 2;
            float* accv = acc[im][in];
            if (MODE == 0) {
                float v0 = gate_act(accv[0], actTanh);
                float v1 = gate_act(accv[1], actTanh);
                float v2 = gate_act(accv[2], actTanh);
                float v3 = gate_act(accv[3], actTanh);
                float* p0 = C + (size_t)r * PPD + c;
                float* p1 = C + (size_t)(r + 8) * PPD + c;
                if (c + 1 < N) {
                    *reinterpret_cast<float2*>(p0) = make_float2(v0, v1);
                    *reinterpret_cast<float2*>(p1) = make_float2(v2, v3);
                } else if (c < N) {
                    *p0 = v0;
                    *p1 = v2;
                }
            } else {
                const float2 x0 = *reinterpret_cast<const float2*>(resid + (size_t)r * N + c);
                const float2 x1 = *reinterpret_cast<const float2*>(resid + (size_t)(r + 8) * N + c);
                *reinterpret_cast<float2*>(C + (size_t)r * N + c) =
                    make_float2(accv[0] + x0.x, accv[1] + x0.y);
                *reinterpret_cast<float2*>(C + (size_t)(r + 8) * N + c) =
                    make_float2(accv[2] + x1.x, accv[3] + x1.y);
            }
        }
    }
}

// ---------------- sequential scan over S ------------------------------------
// one thread per (b, p) chain; deep prefetch (8) to hide DRAM latency
__global__ void scan_kernel(const float* __restrict__ h0, float* __restrict__ hfin) {
    int p = blockIdx.x * blockDim.x + threadIdx.x;
    int b = blockIdx.y;
    if (p >= PD) return;
    float h = h0[(size_t)b * PD + p];
    size_t base = (size_t)b * SS * PPD + p;
    const float* pi = g_gi + base;
    const float* pf = g_gf + base;
    const float* po = g_go + base;
    const float* pc = g_gc + base;
    float* pout = g_act + base;

    constexpr int PF = 8;
    float bi[PF], bf[PF], bo[PF], bc[PF];
    #pragma unroll
    for (int j = 0; j < PF; ++j) {
        size_t o = (size_t)j * PPD;
        bi[j] = pi[o]; bf[j] = pf[o]; bo[j] = po[o]; bc[j] = pc[o];
    }
    #pragma unroll 8
    for (int s = 0; s < SS; ++s) {
        int slot = s & (PF - 1);
        float iv = bi[slot], fv = bf[slot], ov = bo[slot], cv = bc[slot];
        int sn = s + PF;
        if (sn < SS) {
            size_t o = (size_t)sn * PPD;
            bi[slot] = pi[o]; bf[slot] = pf[o]; bo[slot] = po[o]; bc[slot] = pc[o];
        }
        h = fmaf(fv, h, iv * cv);     // h = f*h + i*tanh(c)  (c pre-tanh'd)
        pout[(size_t)s * PPD] = ov * tanhf(h);
    }
    if (hfin) hfin[(size_t)b * PD + p] = h;
}

// ---------------- launch -----------------------------------------------------
extern "C" void kernel_launch(void* const* d_in, const int* in_sizes, int n_in,
                              void* d_out, int out_size) {
    const float* x    = (const float*)d_in[0];
    const float* h0   = (const float*)d_in[1];
    const float* Wi   = (const float*)d_in[2];
    const float* Wf   = (const float*)d_in[3];
    const float* Wo   = (const float*)d_in[4];
    const float* Wc   = (const float*)d_in[5];
    const float* Wout = (const float*)d_in[6];
    const float* lnw  = (const float*)d_in[7];
    float* out = (float*)d_out;

    constexpr int SMEM_BYTES = 3 * 2 * 128 * 36 * 4;  // 110592
    cudaFuncSetAttribute(gemm_tn<0>, cudaFuncAttributeMaxDynamicSharedMemorySize, SMEM_BYTES);
    cudaFuncSetAttribute(gemm_tn<1>, cudaFuncAttributeMaxDynamicSharedMemorySize, SMEM_BYTES);

    // 1) RMSNorm
    rmsnorm_kernel<<<BSD, 256>>>(x, lnw);
    // 2) pad Wout (done early; independent of gates)
    pad_wout_kernel<<<((size_t)DD * PPD + 255) / 256, 256>>>(Wout);
    // 3) four gate GEMMs fused via gridDim.z, activation in epilogue
    gemm_tn<0><<<dim3((PD + 127) / 128, BSD / 128, 4), 256, SMEM_BYTES>>>(
        Wi, Wf, Wo, Wc, nullptr, nullptr, PD, DD, DD, DD);
    // 4) sequential scan; writes g_act and h_final
    float* hfin = nullptr;
    if (out_size >= BSD * DD + BB * PD) hfin = out + (size_t)BSD * DD;
    scan_kernel<<<dim3((PD + 255) / 256, BB), 256>>>(h0, hfin);
    // 5) output GEMM + residual
    gemm_tn<1><<<dim3(DD / 128, BSD / 128, 1), 256, SMEM_BYTES>>>(
        nullptr, nullptr, nullptr, nullptr, x, out, DD, PPD, PPD, PPD);
}

// round 3
// speedup vs baseline: 1.6203x; 1.6203x over previous
#include <cuda_runtime.h>
#include <cuda_fp16.h>
#include <cstdint>
#include <cstddef>

// Shapes: B=4, S=2048, D=2048, P=int(2048*1.333)=2729
#define BSD 8192
#define DD  2048
#define PD  2729
#define PPD 2816          // P padded to multiple of 128 (BN) and 64 (BK)
#define BB  4
#define SS  2048

// ---------------- scratch (device globals) ----------------------------------
__device__ __align__(256) __half g_xn [(size_t)BSD * DD];
__device__ __align__(256) __half g_wi [(size_t)PD * DD];
__device__ __align__(256) __half g_wf [(size_t)PD * DD];
__device__ __align__(256) __half g_wo [(size_t)PD * DD];
__device__ __align__(256) __half g_wc [(size_t)PD * DD];
__device__ __align__(256) __half g_wout[(size_t)DD * PPD];   // padded cols zeroed
__device__ __align__(256) __half g_gi [(size_t)BSD * PPD];
__device__ __align__(256) __half g_gf [(size_t)BSD * PPD];
__device__ __align__(256) __half g_go [(size_t)BSD * PPD];
__device__ __align__(256) __half g_gc [(size_t)BSD * PPD];
__device__ __align__(256) __half g_act[(size_t)BSD * PPD];   // pad cols stay 0 (zero-init)

// ---------------- PTX helpers ------------------------------------------------
__device__ __forceinline__ uint32_t smem_u32(const void* p) {
    uint32_t a;
    asm("{ .reg .u64 t; cvta.to.shared.u64 t, %1; cvt.u32.u64 %0, t; }" : "=r"(a) : "l"(p));
    return a;
}
__device__ __forceinline__ void cp16(uint32_t dst, const void* src, int nbytes) {
    asm volatile("cp.async.cg.shared.global [%0], [%1], 16, %2;\n"
                 :: "r"(dst), "l"(src), "r"(nbytes));
}
__device__ __forceinline__ void cp_commit() { asm volatile("cp.async.commit_group;\n"); }
template<int N> __device__ __forceinline__ void cp_wait() {
    asm volatile("cp.async.wait_group %0;\n" :: "n"(N) : "memory");
}
__device__ __forceinline__ void ldsm4(uint32_t* r, uint32_t addr) {
    asm volatile("ldmatrix.sync.aligned.m8n8.x4.shared.b16 {%0,%1,%2,%3}, [%4];"
                 : "=r"(r[0]), "=r"(r[1]), "=r"(r[2]), "=r"(r[3]) : "r"(addr));
}
// m16n8k16 fp16 in, fp32 accum
__device__ __forceinline__ void mma16(float* c, const uint32_t* a, const uint32_t* b) {
    asm volatile(
        "mma.sync.aligned.m16n8k16.row.col.f32.f16.f16.f32 "
        "{%0,%1,%2,%3}, {%4,%5,%6,%7}, {%8,%9}, {%0,%1,%2,%3};\n"
        : "+f"(c[0]), "+f"(c[1]), "+f"(c[2]), "+f"(c[3])
        : "r"(a[0]), "r"(a[1]), "r"(a[2]), "r"(a[3]), "r"(b[0]), "r"(b[1]));
}

// ---------------- fast activations -------------------------------------------
__device__ __forceinline__ float f_ex2(float x) { float y; asm("ex2.approx.f32 %0, %1;" : "=f"(y) : "f"(x)); return y; }
__device__ __forceinline__ float f_rcp(float x) { float y; asm("rcp.approx.f32 %0, %1;" : "=f"(y) : "f"(x)); return y; }
__device__ __forceinline__ float f_tanh(float x) {
    x = fminf(fmaxf(x, -15.f), 15.f);
    float u = f_ex2(x * 2.885390082f);             // 2^(2x/ln2) = e^{2x}
    return (u - 1.f) * f_rcp(u + 1.f);
}
__device__ __forceinline__ float f_sig(float x) {
    float v = f_ex2(-x * 1.442695041f);
    return f_rcp(1.f + v);
}
__device__ __forceinline__ float gate_act(float z, bool tanhOnly) {
    if (tanhOnly) return f_tanh(z);
    float t = 15.f * f_tanh(z * (1.f / 15.f));     // soft cap
    return f_sig(t);
}

// ---------------- rmsnorm -> fp16 --------------------------------------------
__global__ void rmsnorm_kernel(const float* __restrict__ x, const float* __restrict__ w) {
    int row = blockIdx.x;
    int t = threadIdx.x;
    const float4* xr = reinterpret_cast<const float4*>(x + (size_t)row * DD);
    float4 v0 = xr[t], v1 = xr[t + 256];
    float ss = v0.x*v0.x + v0.y*v0.y + v0.z*v0.z + v0.w*v0.w
             + v1.x*v1.x + v1.y*v1.y + v1.z*v1.z + v1.w*v1.w;
    #pragma unroll
    for (int o = 16; o > 0; o >>= 1) ss += __shfl_xor_sync(0xffffffffu, ss, o);
    __shared__ float red[8];
    if ((t & 31) == 0) red[t >> 5] = ss;
    __syncthreads();
    float tot = red[0]+red[1]+red[2]+red[3]+red[4]+red[5]+red[6]+red[7];
    float r = rsqrtf(tot * (1.0f / DD) + 1e-6f);
    const float4* wr = reinterpret_cast<const float4*>(w);
    float4 w0 = wr[t], w1 = wr[t + 256];
    __half2* dst = reinterpret_cast<__half2*>(g_xn + (size_t)row * DD);
    dst[t*2  ]       = __floats2half2_rn(v0.x*r*w0.x, v0.y*r*w0.y);
    dst[t*2+1]       = __floats2half2_rn(v0.z*r*w0.z, v0.w*r*w0.w);
    dst[(t+256)*2  ] = __floats2half2_rn(v1.x*r*w1.x, v1.y*r*w1.y);
    dst[(t+256)*2+1] = __floats2half2_rn(v1.z*r*w1.z, v1.w*r*w1.w);
}

// ---------------- weight conversion ------------------------------------------
__global__ void convert_w_kernel(const float* __restrict__ W0, const float* __restrict__ W1,
                                 const float* __restrict__ W2, const float* __restrict__ W3) {
    size_t i = (size_t)blockIdx.x * blockDim.x + threadIdx.x;
    if (i >= (size_t)PD * DD) return;
    int z = blockIdx.y;
    const float* src = (z == 0) ? W0 : (z == 1) ? W1 : (z == 2) ? W2 : W3;
    __half* dst = (z == 0) ? g_wi : (z == 1) ? g_wf : (z == 2) ? g_wo : g_wc;
    dst[i] = __float2half_rn(src[i]);
}
__global__ void pad_wout_kernel(const float* __restrict__ wout) {
    size_t i = (size_t)blockIdx.x * blockDim.x + threadIdx.x;
    if (i >= (size_t)DD * PPD) return;
    int d = (int)(i / PPD);
    int p = (int)(i % PPD);
    g_wout[i] = (p < PD) ? __float2half_rn(wout[(size_t)d * PD + p]) : __half(0.f);
}

// ---------------- fp16 TN GEMM: C[M,N] = A[M,K] * B[N,K]^T -------------------
// MODE 0: A=g_xn (half, lda=DD), B=g_w*[z], N=PD, epilogue=gate act -> half plane
// MODE 1: A=g_act (half, lda=PPD), B=g_wout, N=DD, epilogue=+residual -> f32 out
template<int MODE>
__global__ __launch_bounds__(256)
void gemm_fp16(const float* __restrict__ resid, float* __restrict__ outp,
               int Nreal, int KT, int lda, int ldb)
{
    constexpr int BM = 128, BN = 128, BK = 64;
    constexpr int LDH = 72;                 // smem row stride in halves (pad 8)
    constexpr int TILE_B = BM * LDH * 2;    // 18432 bytes per A (or B) tile
    constexpr int STG = 2 * TILE_B;         // 36864 bytes per stage
    extern __shared__ char dsm[];

    const int tid  = threadIdx.x;
    const int lane = tid & 31;
    const int wid  = tid >> 5;
    const int wm   = wid & 3;               // 4 warps along M (32 rows)
    const int wn   = wid >> 2;              // 2 warps along N (64 cols)
    const int m0   = blockIdx.y * BM;
    const int n0   = blockIdx.x * BN;

    const __half* A;
    const __half* Bw;
    __half* C = nullptr;
    bool actTanh = false;
    if (MODE == 0) {
        A = g_xn;
        int z = blockIdx.z;
        Bw = (z == 0) ? g_wi : (z == 1) ? g_wf : (z == 2) ? g_wo : g_wc;
        C  = (z == 0) ? g_gi : (z == 1) ? g_gf : (z == 2) ? g_go : g_gc;
        actTanh = (z == 3);
    } else {
        A = g_act; Bw = g_wout;
    }

    const uint32_t sbase = smem_u32(dsm);

    auto fill = [&](int s, int kt) {
        const int k0 = kt * BK;
        uint32_t ab = sbase + s * STG;
        uint32_t bb = ab + TILE_B;
        #pragma unroll
        for (int i = 0; i < 4; ++i) {
            int idx = tid + i * 256;
            int r = idx >> 3, c = idx & 7;       // r:0..127, c: 16B chunk
            cp16(ab + (r * LDH + c * 8) * 2,
                 A + (size_t)(m0 + r) * lda + k0 + c * 8, 16);
            int nr = n0 + r;
            int ok = (MODE == 1) || (nr < Nreal);
            cp16(bb + (r * LDH + c * 8) * 2,
                 Bw + (size_t)(ok ? nr : 0) * ldb + k0 + c * 8, ok ? 16 : 0);
        }
        cp_commit();
    };

    float acc[2][8][4];
    #pragma unroll
    for (int im = 0; im < 2; ++im)
        #pragma unroll
        for (int in = 0; in < 8; ++in)
            #pragma unroll
            for (int j = 0; j < 4; ++j) acc[im][in][j] = 0.0f;

    // ldmatrix lane offsets (in halves)
    const int a_row = ((lane >> 3) & 1) * 8 + (lane & 7);
    const int a_k   = (lane >> 4) * 8;
    const int b_row = ((lane >> 4) & 1) * 8 + (lane & 7);
    const int b_k   = ((lane >> 3) & 1) * 8;

    fill(0, 0);
    fill(1, 1);
    cp_wait<1>();
    __syncthreads();

    for (int kt = 0; kt < KT; ++kt) {
        int s = kt % 3;
        if (kt + 2 < KT) fill((kt + 2) % 3, kt + 2);
        else cp_commit();

        uint32_t aS = sbase + s * STG;
        uint32_t bS = aS + TILE_B;

        #pragma unroll
        for (int ks = 0; ks < 4; ++ks) {
            uint32_t ra[2][4];
            uint32_t rb[8][2];
            #pragma unroll
            for (int im = 0; im < 2; ++im) {
                uint32_t addr = aS + ((wm * 32 + im * 16 + a_row) * LDH + ks * 16 + a_k) * 2;
                ldsm4(ra[im], addr);
            }
            #pragma unroll
            for (int ip = 0; ip < 4; ++ip) {     // pairs (in=2ip, 2ip+1)
                uint32_t r4[4];
                uint32_t addr = bS + ((wn * 64 + ip * 16 + b_row) * LDH + ks * 16 + b_k) * 2;
                ldsm4(r4, addr);
                rb[2*ip  ][0] = r4[0]; rb[2*ip  ][1] = r4[1];
                rb[2*ip+1][0] = r4[2]; rb[2*ip+1][1] = r4[3];
            }
            #pragma unroll
            for (int im = 0; im < 2; ++im)
                #pragma unroll
                for (int in = 0; in < 8; ++in)
                    mma16(acc[im][in], ra[im], rb[in]);
        }
        cp_wait<1>();
        __syncthreads();
    }

    // ---- epilogue ----
    const int qr = lane >> 2;        // 0..7
    const int qc = lane & 3;         // 0..3
    #pragma unroll
    for (int im = 0; im < 2; ++im) {
        int row = m0 + wm * 32 + im * 16 + qr;
        #pragma unroll
        for (int in = 0; in < 8; ++in) {
            int col = n0 + wn * 64 + in * 8 + qc * 2;
            float* a = acc[im][in];
            if (MODE == 0) {
                float v0 = gate_act(a[0], actTanh);
                float v1 = gate_act(a[1], actTanh);
                float v2 = gate_act(a[2], actTanh);
                float v3 = gate_act(a[3], actTanh);
                __half* p0 = C + (size_t)row * PPD + col;
                __half* p1 = C + (size_t)(row + 8) * PPD + col;
                if (col + 1 < Nreal) {
                    *reinterpret_cast<__half2*>(p0) = __floats2half2_rn(v0, v1);
                    *reinterpret_cast<__half2*>(p1) = __floats2half2_rn(v2, v3);
                } else if (col < Nreal) {
                    *p0 = __float2half_rn(v0);
                    *p1 = __float2half_rn(v2);
                }
            } else {
                const float2 x0 = *reinterpret_cast<const float2*>(resid + (size_t)row * DD + col);
                const float2 x1 = *reinterpret_cast<const float2*>(resid + (size_t)(row + 8) * DD + col);
                *reinterpret_cast<float2*>(outp + (size_t)row * DD + col) =
                    make_float2(a[0] + x0.x, a[1] + x0.y);
                *reinterpret_cast<float2*>(outp + (size_t)(row + 8) * DD + col) =
                    make_float2(a[2] + x1.x, a[3] + x1.y);
            }
        }
    }
}

// ---------------- sequential scan over S -------------------------------------
__global__ void scan_kernel(const float* __restrict__ h0, float* __restrict__ hfin) {
    int p = blockIdx.x * blockDim.x + threadIdx.x;
    int b = blockIdx.y;
    if (p >= PD) return;
    float h = h0[(size_t)b * PD + p];
    size_t base = (size_t)b * SS * PPD + p;
    const __half* pi = g_gi + base;
    const __half* pf = g_gf + base;
    const __half* po = g_go + base;
    const __half* pc = g_gc + base;
    __half* pout = g_act + base;

    constexpr int PF = 8;
    __half bi[PF], bf[PF], bo[PF], bc[PF];
    #pragma unroll
    for (int j = 0; j < PF; ++j) {
        size_t o = (size_t)j * PPD;
        bi[j] = pi[o]; bf[j] = pf[o]; bo[j] = po[o]; bc[j] = pc[o];
    }
    #pragma unroll 8
    for (int s = 0; s < SS; ++s) {
        int slot = s & (PF - 1);
        float iv = __half2float(bi[slot]);
        float fv = __half2float(bf[slot]);
        float ov = __half2float(bo[slot]);
        float cv = __half2float(bc[slot]);
        int sn = s + PF;
        if (sn < SS) {
            size_t o = (size_t)sn * PPD;
            bi[slot] = pi[o]; bf[slot] = pf[o]; bo[slot] = po[o]; bc[slot] = pc[o];
        }
        h = fmaf(fv, h, iv * cv);                  // c already tanh'ed
        pout[(size_t)s * PPD] = __float2half_rn(ov * f_tanh(h));
    }
    if (hfin) hfin[(size_t)b * PD + p] = h;
}

// ---------------- launch -----------------------------------------------------
extern "C" void kernel_launch(void* const* d_in, const int* in_sizes, int n_in,
                              void* d_out, int out_size) {
    const float* x    = (const float*)d_in[0];
    const float* h0   = (const float*)d_in[1];
    const float* Wi   = (const float*)d_in[2];
    const float* Wf   = (const float*)d_in[3];
    const float* Wo   = (const float*)d_in[4];
    const float* Wc   = (const float*)d_in[5];
    const float* Wout = (const float*)d_in[6];
    const float* lnw  = (const float*)d_in[7];
    float* out = (float*)d_out;

    constexpr int SMEM_BYTES = 3 * 2 * 128 * 72 * 2;   // 110592
    cudaFuncSetAttribute(gemm_fp16<0>, cudaFuncAttributeMaxDynamicSharedMemorySize, SMEM_BYTES);
    cudaFuncSetAttribute(gemm_fp16<1>, cudaFuncAttributeMaxDynamicSharedMemorySize, SMEM_BYTES);

    rmsnorm_kernel<<<BSD, 256>>>(x, lnw);
    convert_w_kernel<<<dim3(((size_t)PD * DD + 255) / 256, 4), 256>>>(Wi, Wf, Wo, Wc);
    pad_wout_kernel<<<((size_t)DD * PPD + 255) / 256, 256>>>(Wout);

    // gates: M=8192, N=PD (tiles to PPD), K=2048
    gemm_fp16<0><<<dim3(PPD / 128, BSD / 128, 4), 256, SMEM_BYTES>>>(
        nullptr, nullptr, PD, DD / 64, DD, DD);

    float* hfin = nullptr;
    if (out_size >= BSD * DD + BB * PD) hfin = out + (size_t)BSD * DD;
    scan_kernel<<<dim3((PD + 63) / 64, BB), 64>>>(h0, hfin);

    // out: M=8192, N=2048, K=PPD (act pad cols are zero)
    gemm_fp16<1><<<dim3(DD / 128, BSD / 128, 1), 256, SMEM_BYTES>>>(
        x, out, DD, PPD / 64, PPD, PPD);
}

// round 4
// speedup vs baseline: 2.1821x; 1.3467x over previous
#include <cuda_runtime.h>
#include <cuda_fp16.h>
#include <cstdint>
#include <cstddef>

// Shapes: B=4, S=2048, D=2048, P=int(2048*1.333)=2729
#define BSD 8192
#define DD  2048
#define PD  2729
#define PPD 2816          // P padded to multiple of 128 (BN) and 64 (BK)
#define BB  4
#define SS  2048

// ---------------- scratch (device globals) ----------------------------------
__device__ __align__(256) __half g_xn [(size_t)BSD * DD];
__device__ __align__(256) __half g_wi [(size_t)PD * DD];
__device__ __align__(256) __half g_wf [(size_t)PD * DD];
__device__ __align__(256) __half g_wo [(size_t)PD * DD];
__device__ __align__(256) __half g_wc [(size_t)PD * DD];
__device__ __align__(256) __half g_wout[(size_t)DD * PPD];   // padded cols zeroed
__device__ __align__(256) __half g_gi [(size_t)BSD * PPD];
__device__ __align__(256) __half g_gf [(size_t)BSD * PPD];
__device__ __align__(256) __half g_go [(size_t)BSD * PPD];
__device__ __align__(256) __half g_gc [(size_t)BSD * PPD];
__device__ __align__(256) __half g_act[(size_t)BSD * PPD];   // pad cols stay 0 (zero-init)

// ---------------- PTX helpers ------------------------------------------------
__device__ __forceinline__ uint32_t smem_u32(const void* p) {
    uint32_t a;
    asm("{ .reg .u64 t; cvta.to.shared.u64 t, %1; cvt.u32.u64 %0, t; }" : "=r"(a) : "l"(p));
    return a;
}
__device__ __forceinline__ void cp16(uint32_t dst, const void* src, int nbytes) {
    asm volatile("cp.async.cg.shared.global [%0], [%1], 16, %2;\n"
                 :: "r"(dst), "l"(src), "r"(nbytes));
}
__device__ __forceinline__ void cp_commit() { asm volatile("cp.async.commit_group;\n"); }
template<int N> __device__ __forceinline__ void cp_wait() {
    asm volatile("cp.async.wait_group %0;\n" :: "n"(N) : "memory");
}
__device__ __forceinline__ void ldsm4(uint32_t* r, uint32_t addr) {
    asm volatile("ldmatrix.sync.aligned.m8n8.x4.shared.b16 {%0,%1,%2,%3}, [%4];"
                 : "=r"(r[0]), "=r"(r[1]), "=r"(r[2]), "=r"(r[3]) : "r"(addr));
}
// m16n8k16 fp16 in, fp32 accum
__device__ __forceinline__ void mma16(float* c, const uint32_t* a, const uint32_t* b) {
    asm volatile(
        "mma.sync.aligned.m16n8k16.row.col.f32.f16.f16.f32 "
        "{%0,%1,%2,%3}, {%4,%5,%6,%7}, {%8,%9}, {%0,%1,%2,%3};\n"
        : "+f"(c[0]), "+f"(c[1]), "+f"(c[2]), "+f"(c[3])
        : "r"(a[0]), "r"(a[1]), "r"(a[2]), "r"(a[3]), "r"(b[0]), "r"(b[1]));
}

// ---------------- fast activations -------------------------------------------
__device__ __forceinline__ float f_ex2(float x) { float y; asm("ex2.approx.f32 %0, %1;" : "=f"(y) : "f"(x)); return y; }
__device__ __forceinline__ float f_rcp(float x) { float y; asm("rcp.approx.f32 %0, %1;" : "=f"(y) : "f"(x)); return y; }
__device__ __forceinline__ float f_tanh(float x) {
    x = fminf(fmaxf(x, -15.f), 15.f);
    float u = f_ex2(x * 2.885390082f);             // e^{2x}
    return (u - 1.f) * f_rcp(u + 1.f);
}
__device__ __forceinline__ float f_sig(float x) {
    float v = f_ex2(-x * 1.442695041f);
    return f_rcp(1.f + v);
}
__device__ __forceinline__ float gate_act(float z, bool tanhOnly) {
    if (tanhOnly) return f_tanh(z);
    float t = 15.f * f_tanh(z * (1.f / 15.f));     // soft cap
    return f_sig(t);
}

// ---------------- rmsnorm -> fp16 --------------------------------------------
__global__ void rmsnorm_kernel(const float* __restrict__ x, const float* __restrict__ w) {
    int row = blockIdx.x;
    int t = threadIdx.x;
    const float4* xr = reinterpret_cast<const float4*>(x + (size_t)row * DD);
    float4 v0 = xr[t], v1 = xr[t + 256];
    float ss = v0.x*v0.x + v0.y*v0.y + v0.z*v0.z + v0.w*v0.w
             + v1.x*v1.x + v1.y*v1.y + v1.z*v1.z + v1.w*v1.w;
    #pragma unroll
    for (int o = 16; o > 0; o >>= 1) ss += __shfl_xor_sync(0xffffffffu, ss, o);
    __shared__ float red[8];
    if ((t & 31) == 0) red[t >> 5] = ss;
    __syncthreads();
    float tot = red[0]+red[1]+red[2]+red[3]+red[4]+red[5]+red[6]+red[7];
    float r = rsqrtf(tot * (1.0f / DD) + 1e-6f);
    const float4* wr = reinterpret_cast<const float4*>(w);
    float4 w0 = wr[t], w1 = wr[t + 256];
    __half2* dst = reinterpret_cast<__half2*>(g_xn + (size_t)row * DD);
    dst[t*2  ]       = __floats2half2_rn(v0.x*r*w0.x, v0.y*r*w0.y);
    dst[t*2+1]       = __floats2half2_rn(v0.z*r*w0.z, v0.w*r*w0.w);
    dst[(t+256)*2  ] = __floats2half2_rn(v1.x*r*w1.x, v1.y*r*w1.y);
    dst[(t+256)*2+1] = __floats2half2_rn(v1.z*r*w1.z, v1.w*r*w1.w);
}

// ---------------- weight conversion ------------------------------------------
__global__ void convert_w_kernel(const float* __restrict__ W0, const float* __restrict__ W1,
                                 const float* __restrict__ W2, const float* __restrict__ W3) {
    size_t i = (size_t)blockIdx.x * blockDim.x + threadIdx.x;
    if (i >= (size_t)PD * DD) return;
    int z = blockIdx.y;
    const float* src = (z == 0) ? W0 : (z == 1) ? W1 : (z == 2) ? W2 : W3;
    __half* dst = (z == 0) ? g_wi : (z == 1) ? g_wf : (z == 2) ? g_wo : g_wc;
    dst[i] = __float2half_rn(src[i]);
}
__global__ void pad_wout_kernel(const float* __restrict__ wout) {
    size_t i = (size_t)blockIdx.x * blockDim.x + threadIdx.x;
    if (i >= (size_t)DD * PPD) return;
    int d = (int)(i / PPD);
    int p = (int)(i % PPD);
    g_wout[i] = (p < PD) ? __float2half_rn(wout[(size_t)d * PD + p]) : __half(0.f);
}

// ---------------- fp16 TN GEMM: C[M,N] = A[M,K] * B[N,K]^T -------------------
// XOR-swizzled smem (row = 128B exactly): chunk c (16B) of row r lives at
// byte r*128 + (c ^ (r&7))*16. 3 stages = 96KB/CTA -> 2 CTAs/SM.
// MODE 0: A=g_xn, B=g_w*[z], N=PD, epilogue=gate act -> half plane
// MODE 1: A=g_act, B=g_wout, N=DD, epilogue=+residual -> f32 out
template<int MODE>
__global__ __launch_bounds__(256, 2)
void gemm_fp16(const float* __restrict__ resid, float* __restrict__ outp,
               int Nreal, int KT, int lda, int ldb)
{
    constexpr int BM = 128, BN = 128, BK = 64;
    constexpr int TILE_B = BM * 128;        // 16384 bytes per tile (A or B)
    constexpr int STG = 2 * TILE_B;         // 32768 bytes per stage
    extern __shared__ char dsm[];

    const int tid  = threadIdx.x;
    const int lane = tid & 31;
    const int wid  = tid >> 5;
    const int wm   = wid & 3;               // 4 warps along M (32 rows)
    const int wn   = wid >> 2;              // 2 warps along N (64 cols)
    const int m0   = blockIdx.y * BM;
    const int n0   = blockIdx.x * BN;

    const __half* A;
    const __half* Bw;
    __half* C = nullptr;
    bool actTanh = false;
    if (MODE == 0) {
        A = g_xn;
        int z = blockIdx.z;
        Bw = (z == 0) ? g_wi : (z == 1) ? g_wf : (z == 2) ? g_wo : g_wc;
        C  = (z == 0) ? g_gi : (z == 1) ? g_gf : (z == 2) ? g_go : g_gc;
        actTanh = (z == 3);
    } else {
        A = g_act; Bw = g_wout;
    }

    const uint32_t sbase = smem_u32(dsm);

    auto fill = [&](int s, int kt) {
        const int k0 = kt * BK;
        uint32_t ab = sbase + s * STG;
        uint32_t bb = ab + TILE_B;
        #pragma unroll
        for (int i = 0; i < 4; ++i) {
            int idx = tid + i * 256;
            int r = idx >> 3, c = idx & 7;            // row, 16B chunk
            uint32_t off = r * 128 + ((c ^ (r & 7)) << 4);
            cp16(ab + off, A + (size_t)(m0 + r) * lda + k0 + c * 8, 16);
            int nr = n0 + r;
            int ok = (MODE == 1) || (nr < Nreal);
            cp16(bb + off, Bw + (size_t)(ok ? nr : 0) * ldb + k0 + c * 8, ok ? 16 : 0);
        }
        cp_commit();
    };

    float acc[2][8][4];
    #pragma unroll
    for (int im = 0; im < 2; ++im)
        #pragma unroll
        for (int in = 0; in < 8; ++in)
            #pragma unroll
            for (int j = 0; j < 4; ++j) acc[im][in][j] = 0.0f;

    // ldmatrix lane row/chunk mapping
    const int a_row = ((lane >> 3) & 1) * 8 + (lane & 7);   // row within 16
    const int a_ch  = (lane >> 4);                          // 0 or 1 (k halves 0/8)
    const int b_row = ((lane >> 4) & 1) * 8 + (lane & 7);
    const int b_ch  = (lane >> 3) & 1;

    fill(0, 0);
    fill(1, 1);
    cp_wait<1>();
    __syncthreads();

    for (int kt = 0; kt < KT; ++kt) {
        int s = kt % 3;
        if (kt + 2 < KT) fill((kt + 2) % 3, kt + 2);
        else cp_commit();

        uint32_t aS = sbase + s * STG;
        uint32_t bS = aS + TILE_B;

        #pragma unroll
        for (int ks = 0; ks < 4; ++ks) {
            uint32_t ra[2][4];
            #pragma unroll
            for (int im = 0; im < 2; ++im) {
                int row = wm * 32 + im * 16 + a_row;
                int ch  = ks * 2 + a_ch;
                ldsm4(ra[im], aS + row * 128 + (((ch ^ (row & 7)) & 7) << 4));
            }
            #pragma unroll
            for (int ip = 0; ip < 4; ++ip) {
                uint32_t r4[4];
                int row = wn * 64 + ip * 16 + b_row;
                int ch  = ks * 2 + b_ch;
                ldsm4(r4, bS + row * 128 + (((ch ^ (row & 7)) & 7) << 4));
                #pragma unroll
                for (int im = 0; im < 2; ++im) {
                    mma16(acc[im][2*ip    ], ra[im], r4);
                    mma16(acc[im][2*ip + 1], ra[im], r4 + 2);
                }
            }
        }
        cp_wait<1>();
        __syncthreads();
    }

    // ---- epilogue ----
    const int qr = lane >> 2;        // 0..7
    const int qc = lane & 3;         // 0..3
    #pragma unroll
    for (int im = 0; im < 2; ++im) {
        int row = m0 + wm * 32 + im * 16 + qr;
        #pragma unroll
        for (int in = 0; in < 8; ++in) {
            int col = n0 + wn * 64 + in * 8 + qc * 2;
            float* a = acc[im][in];
            if (MODE == 0) {
                float v0 = gate_act(a[0], actTanh);
                float v1 = gate_act(a[1], actTanh);
                float v2 = gate_act(a[2], actTanh);
                float v3 = gate_act(a[3], actTanh);
                __half* p0 = C + (size_t)row * PPD + col;
                __half* p1 = C + (size_t)(row + 8) * PPD + col;
                if (col + 1 < Nreal) {
                    *reinterpret_cast<__half2*>(p0) = __floats2half2_rn(v0, v1);
                    *reinterpret_cast<__half2*>(p1) = __floats2half2_rn(v2, v3);
                } else if (col < Nreal) {
                    *p0 = __float2half_rn(v0);
                    *p1 = __float2half_rn(v2);
                }
            } else {
                const float2 x0 = *reinterpret_cast<const float2*>(resid + (size_t)row * DD + col);
                const float2 x1 = *reinterpret_cast<const float2*>(resid + (size_t)(row + 8) * DD + col);
                *reinterpret_cast<float2*>(outp + (size_t)row * DD + col) =
                    make_float2(a[0] + x0.x, a[1] + x0.y);
                *reinterpret_cast<float2*>(outp + (size_t)(row + 8) * DD + col) =
                    make_float2(a[2] + x1.x, a[3] + x1.y);
            }
        }
    }
}

// ---------------- sequential scan over S -------------------------------------
__global__ void scan_kernel(const float* __restrict__ h0, float* __restrict__ hfin) {
    int p = blockIdx.x * blockDim.x + threadIdx.x;
    int b = blockIdx.y;
    if (p >= PD) return;
    float h = h0[(size_t)b * PD + p];
    size_t base = (size_t)b * SS * PPD + p;
    const __half* pi = g_gi + base;
    const __half* pf = g_gf + base;
    const __half* po = g_go + base;
    const __half* pc = g_gc + base;
    __half* pout = g_act + base;

    constexpr int PF = 8;
    __half bi[PF], bf[PF], bo[PF], bc[PF];
    #pragma unroll
    for (int j = 0; j < PF; ++j) {
        size_t o = (size_t)j * PPD;
        bi[j] = pi[o]; bf[j] = pf[o]; bo[j] = po[o]; bc[j] = pc[o];
    }
    #pragma unroll 8
    for (int s = 0; s < SS; ++s) {
        int slot = s & (PF - 1);
        float iv = __half2float(bi[slot]);
        float fv = __half2float(bf[slot]);
        float ov = __half2float(bo[slot]);
        float cv = __half2float(bc[slot]);
        int sn = s + PF;
        if (sn < SS) {
            size_t o = (size_t)sn * PPD;
            bi[slot] = pi[o]; bf[slot] = pf[o]; bo[slot] = po[o]; bc[slot] = pc[o];
        }
        h = fmaf(fv, h, iv * cv);                  // c already tanh'ed
        pout[(size_t)s * PPD] = __float2half_rn(ov * f_tanh(h));
    }
    if (hfin) hfin[(size_t)b * PD + p] = h;
}

// ---------------- launch -----------------------------------------------------
extern "C" void kernel_launch(void* const* d_in, const int* in_sizes, int n_in,
                              void* d_out, int out_size) {
    const float* x    = (const float*)d_in[0];
    const float* h0   = (const float*)d_in[1];
    const float* Wi   = (const float*)d_in[2];
    const float* Wf   = (const float*)d_in[3];
    const float* Wo   = (const float*)d_in[4];
    const float* Wc   = (const float*)d_in[5];
    const float* Wout = (const float*)d_in[6];
    const float* lnw  = (const float*)d_in[7];
    float* out = (float*)d_out;

    constexpr int SMEM_BYTES = 3 * 2 * 128 * 128;      // 98304 (3 stages, A+B)
    cudaFuncSetAttribute(gemm_fp16<0>, cudaFuncAttributeMaxDynamicSharedMemorySize, SMEM_BYTES);
    cudaFuncSetAttribute(gemm_fp16<1>, cudaFuncAttributeMaxDynamicSharedMemorySize, SMEM_BYTES);

    rmsnorm_kernel<<<BSD, 256>>>(x, lnw);
    convert_w_kernel<<<dim3(((size_t)PD * DD + 255) / 256, 4), 256>>>(Wi, Wf, Wo, Wc);
    pad_wout_kernel<<<((size_t)DD * PPD + 255) / 256, 256>>>(Wout);

    // gates: M=8192, N=PD (tiles to PPD), K=2048
    gemm_fp16<0><<<dim3(PPD / 128, BSD / 128, 4), 256, SMEM_BYTES>>>(
        nullptr, nullptr, PD, DD / 64, DD, DD);

    float* hfin = nullptr;
    if (out_size >= BSD * DD + BB * PD) hfin = out + (size_t)BSD * DD;
    scan_kernel<<<dim3((PD + 63) / 64, BB), 64>>>(h0, hfin);

    // out: M=8192, N=2048, K=PPD (act pad cols are zero)
    gemm_fp16<1><<<dim3(DD / 128, BSD / 128, 1), 256, SMEM_BYTES>>>(
        x, out, DD, PPD / 64, PPD, PPD);
}

// round 5
// speedup vs baseline: 2.4860x; 1.1393x over previous
#include <cuda_runtime.h>
#include <cuda_fp16.h>
#include <cstdint>
#include <cstddef>

// Shapes: B=4, S=2048, D=2048, P=int(2048*1.333)=2729
#define BSD 8192
#define DD  2048
#define PD  2729
#define PPD 2816          // P padded to multiple of 128 (BN) and 64 (BK)
#define BB  4
#define SS  2048

// ---------------- scratch (device globals) ----------------------------------
__device__ __align__(256) __half g_xn [(size_t)BSD * DD];
__device__ __align__(256) __half g_wi [(size_t)PD * DD];
__device__ __align__(256) __half g_wf [(size_t)PD * DD];
__device__ __align__(256) __half g_wo [(size_t)PD * DD];
__device__ __align__(256) __half g_wc [(size_t)PD * DD];
__device__ __align__(256) __half g_wout[(size_t)DD * PPD];   // padded cols zeroed
__device__ __align__(256) __half g_gi [(size_t)BSD * PPD];
__device__ __align__(256) __half g_gf [(size_t)BSD * PPD];
__device__ __align__(256) __half g_go [(size_t)BSD * PPD];
__device__ __align__(256) __half g_gc [(size_t)BSD * PPD];
__device__ __align__(256) __half g_act[(size_t)BSD * PPD];   // pad cols stay 0 (zero-init)

// ---------------- PTX helpers ------------------------------------------------
__device__ __forceinline__ uint32_t smem_u32(const void* p) {
    uint32_t a;
    asm("{ .reg .u64 t; cvta.to.shared.u64 t, %1; cvt.u32.u64 %0, t; }" : "=r"(a) : "l"(p));
    return a;
}
__device__ __forceinline__ void cp16(uint32_t dst, const void* src, int nbytes) {
    asm volatile("cp.async.cg.shared.global [%0], [%1], 16, %2;\n"
                 :: "r"(dst), "l"(src), "r"(nbytes));
}
__device__ __forceinline__ void cp_commit() { asm volatile("cp.async.commit_group;\n"); }
template<int N> __device__ __forceinline__ void cp_wait() {
    asm volatile("cp.async.wait_group %0;\n" :: "n"(N) : "memory");
}
__device__ __forceinline__ void ldsm4(uint32_t* r, uint32_t addr) {
    asm volatile("ldmatrix.sync.aligned.m8n8.x4.shared.b16 {%0,%1,%2,%3}, [%4];"
                 : "=r"(r[0]), "=r"(r[1]), "=r"(r[2]), "=r"(r[3]) : "r"(addr));
}
// m16n8k16 fp16 in, fp32 accum
__device__ __forceinline__ void mma16(float* c, const uint32_t* a, const uint32_t* b) {
    asm volatile(
        "mma.sync.aligned.m16n8k16.row.col.f32.f16.f16.f32 "
        "{%0,%1,%2,%3}, {%4,%5,%6,%7}, {%8,%9}, {%0,%1,%2,%3};\n"
        : "+f"(c[0]), "+f"(c[1]), "+f"(c[2]), "+f"(c[3])
        : "r"(a[0]), "r"(a[1]), "r"(a[2]), "r"(a[3]), "r"(b[0]), "r"(b[1]));
}

// ---------------- fast activations -------------------------------------------
__device__ __forceinline__ float f_ex2(float x) { float y; asm("ex2.approx.f32 %0, %1;" : "=f"(y) : "f"(x)); return y; }
__device__ __forceinline__ float f_rcp(float x) { float y; asm("rcp.approx.f32 %0, %1;" : "=f"(y) : "f"(x)); return y; }
__device__ __forceinline__ float f_tanh(float x) {
    x = fminf(fmaxf(x, -15.f), 15.f);
    float u = f_ex2(x * 2.885390082f);             // e^{2x}
    return (u - 1.f) * f_rcp(u + 1.f);
}
__device__ __forceinline__ float f_sig(float x) {
    float v = f_ex2(-x * 1.442695041f);
    return f_rcp(1.f + v);
}
__device__ __forceinline__ float gate_act(float z, bool tanhOnly) {
    if (tanhOnly) return f_tanh(z);
    float t = 15.f * f_tanh(z * (1.f / 15.f));     // soft cap
    return f_sig(t);
}

// ---------------- rmsnorm -> fp16 --------------------------------------------
__global__ void rmsnorm_kernel(const float* __restrict__ x, const float* __restrict__ w) {
    int row = blockIdx.x;
    int t = threadIdx.x;
    const float4* xr = reinterpret_cast<const float4*>(x + (size_t)row * DD);
    float4 v0 = xr[t], v1 = xr[t + 256];
    float ss = v0.x*v0.x + v0.y*v0.y + v0.z*v0.z + v0.w*v0.w
             + v1.x*v1.x + v1.y*v1.y + v1.z*v1.z + v1.w*v1.w;
    #pragma unroll
    for (int o = 16; o > 0; o >>= 1) ss += __shfl_xor_sync(0xffffffffu, ss, o);
    __shared__ float red[8];
    if ((t & 31) == 0) red[t >> 5] = ss;
    __syncthreads();
    float tot = red[0]+red[1]+red[2]+red[3]+red[4]+red[5]+red[6]+red[7];
    float r = rsqrtf(tot * (1.0f / DD) + 1e-6f);
    const float4* wr = reinterpret_cast<const float4*>(w);
    float4 w0 = wr[t], w1 = wr[t + 256];
    __half2* dst = reinterpret_cast<__half2*>(g_xn + (size_t)row * DD);
    dst[t*2  ]       = __floats2half2_rn(v0.x*r*w0.x, v0.y*r*w0.y);
    dst[t*2+1]       = __floats2half2_rn(v0.z*r*w0.z, v0.w*r*w0.w);
    dst[(t+256)*2  ] = __floats2half2_rn(v1.x*r*w1.x, v1.y*r*w1.y);
    dst[(t+256)*2+1] = __floats2half2_rn(v1.z*r*w1.z, v1.w*r*w1.w);
}

// ---------------- weight conversion (vectorized) -----------------------------
// z = 0..3 : gate weights (PD*DD each, divisible by 4)
__global__ void convert_w_kernel(const float* __restrict__ W0, const float* __restrict__ W1,
                                 const float* __restrict__ W2, const float* __restrict__ W3) {
    size_t i4 = (size_t)blockIdx.x * blockDim.x + threadIdx.x;
    if (i4 >= (size_t)PD * DD / 4) return;
    int z = blockIdx.y;
    const float* src = (z == 0) ? W0 : (z == 1) ? W1 : (z == 2) ? W2 : W3;
    __half* dst = (z == 0) ? g_wi : (z == 1) ? g_wf : (z == 2) ? g_wo : g_wc;
    float4 v = reinterpret_cast<const float4*>(src)[i4];
    __half2 h0 = __floats2half2_rn(v.x, v.y);
    __half2 h1 = __floats2half2_rn(v.z, v.w);
    *reinterpret_cast<uint2*>(dst + i4 * 4) =
        make_uint2(*reinterpret_cast<uint32_t*>(&h0), *reinterpret_cast<uint32_t*>(&h1));
}
__global__ void pad_wout_kernel(const float* __restrict__ wout) {
    // one thread per 4 output halves; PPD % 4 == 0
    size_t i4 = (size_t)blockIdx.x * blockDim.x + threadIdx.x;
    if (i4 >= (size_t)DD * PPD / 4) return;
    int d = (int)(i4 / (PPD / 4));
    int p = (int)(i4 % (PPD / 4)) * 4;
    const float* src = wout + (size_t)d * PD + p;
    float a0 = (p     < PD) ? src[0] : 0.f;
    float a1 = (p + 1 < PD) ? src[1] : 0.f;
    float a2 = (p + 2 < PD) ? src[2] : 0.f;
    float a3 = (p + 3 < PD) ? src[3] : 0.f;
    __half2 h0 = __floats2half2_rn(a0, a1);
    __half2 h1 = __floats2half2_rn(a2, a3);
    *reinterpret_cast<uint2*>(g_wout + i4 * 4) =
        make_uint2(*reinterpret_cast<uint32_t*>(&h0), *reinterpret_cast<uint32_t*>(&h1));
}

// ---------------- fp16 TN GEMM: C[M,N] = A[M,K] * B[N,K]^T -------------------
// XOR-swizzled smem (row = 128B): chunk c of row r at byte r*128 + ((c^(r&7))<<4).
// All ldmatrix fragment rows share (row&7)==(lane&7), so per-ks swizzle deltas
// are a single shared term dks = ((2ks)^(lane&6))<<4 added to precomputed bases.
template<int MODE>
__global__ __launch_bounds__(256, 2)
void gemm_fp16(const float* __restrict__ resid, float* __restrict__ outp,
               int Nreal, int KT, int lda, int ldb)
{
    constexpr int BM = 128, BN = 128, BK = 64;
    constexpr int TILE_B = BM * 128;        // 16384 bytes per tile (A or B)
    constexpr int STG = 2 * TILE_B;         // 32768 bytes per stage
    extern __shared__ char dsm[];

    const int tid  = threadIdx.x;
    const int lane = tid & 31;
    const int wid  = tid >> 5;
    const int wm   = wid & 3;               // 4 warps along M (32 rows)
    const int wn   = wid >> 2;              // 2 warps along N (64 cols)
    const int m0   = blockIdx.y * BM;
    const int n0   = blockIdx.x * BN;

    const __half* A;
    const __half* Bw;
    __half* C = nullptr;
    bool actTanh = false;
    if (MODE == 0) {
        A = g_xn;
        int z = blockIdx.z;
        Bw = (z == 0) ? g_wi : (z == 1) ? g_wf : (z == 2) ? g_wo : g_wc;
        C  = (z == 0) ? g_gi : (z == 1) ? g_gf : (z == 2) ? g_go : g_gc;
        actTanh = (z == 3);
    } else {
        A = g_act; Bw = g_wout;
    }

    const uint32_t sbase = smem_u32(dsm);

    auto fill = [&](int s, int kt) {
        const int k0 = kt * BK;
        uint32_t ab = sbase + s * STG;
        uint32_t bb = ab + TILE_B;
        #pragma unroll
        for (int i = 0; i < 4; ++i) {
            int idx = tid + i * 256;
            int r = idx >> 3, c = idx & 7;            // row, 16B chunk
            uint32_t off = r * 128 + ((c ^ (r & 7)) << 4);
            cp16(ab + off, A + (size_t)(m0 + r) * lda + k0 + c * 8, 16);
            int nr = n0 + r;
            int ok = (MODE == 1) || (nr < Nreal);
            cp16(bb + off, Bw + (size_t)(ok ? nr : 0) * ldb + k0 + c * 8, ok ? 16 : 0);
        }
        cp_commit();
    };

    float acc[2][8][4];
    #pragma unroll
    for (int im = 0; im < 2; ++im)
        #pragma unroll
        for (int in = 0; in < 8; ++in)
            #pragma unroll
            for (int j = 0; j < 4; ++j) acc[im][in][j] = 0.0f;

    // ---- precomputed ldmatrix addresses --------------------------------------
    const int l7 = lane & 7, l6 = lane & 6, l1 = lane & 1;
    const int a_row = ((lane >> 3) & 1) * 8 + l7;
    const int a_ch  = (lane >> 4);                   // 0/1
    const int b_row = ((lane >> 4) & 1) * 8 + l7;
    const int b_ch  = (lane >> 3) & 1;
    uint32_t baseA[2], baseB[4], dks[4];
    #pragma unroll
    for (int im = 0; im < 2; ++im)
        baseA[im] = (uint32_t)((wm * 32 + im * 16 + a_row) * 128 + ((a_ch ^ l1) << 4));
    #pragma unroll
    for (int ip = 0; ip < 4; ++ip)
        baseB[ip] = (uint32_t)(TILE_B + (wn * 64 + ip * 16 + b_row) * 128 + ((b_ch ^ l1) << 4));
    #pragma unroll
    for (int ks = 0; ks < 4; ++ks)
        dks[ks] = (uint32_t)(((2 * ks) ^ l6) << 4);

    fill(0, 0);
    fill(1, 1);
    cp_wait<1>();
    __syncthreads();

    int s = 0, sf = 2;          // current stage, next-fill stage
    for (int kt = 0; kt < KT; ++kt) {
        if (kt + 2 < KT) { fill(sf, kt + 2); if (++sf == 3) sf = 0; }
        else cp_commit();

        uint32_t stA = sbase + s * STG;

        #pragma unroll
        for (int ks = 0; ks < 4; ++ks) {
            const uint32_t d = dks[ks];
            uint32_t ra[2][4];
            #pragma unroll
            for (int im = 0; im < 2; ++im)
                ldsm4(ra[im], stA + baseA[im] + d);
            #pragma unroll
            for (int ip = 0; ip < 4; ++ip) {
                uint32_t r4[4];
                ldsm4(r4, stA + baseB[ip] + d);
                #pragma unroll
                for (int im = 0; im < 2; ++im) {
                    mma16(acc[im][2*ip    ], ra[im], r4);
                    mma16(acc[im][2*ip + 1], ra[im], r4 + 2);
                }
            }
        }
        cp_wait<1>();
        __syncthreads();
        if (++s == 3) s = 0;
    }

    // ---- epilogue (branch-free stores; gate-plane pad cols are never read) ---
    const int qr = lane >> 2;        // 0..7
    const int qc = lane & 3;         // 0..3
    #pragma unroll
    for (int im = 0; im < 2; ++im) {
        int row = m0 + wm * 32 + im * 16 + qr;
        #pragma unroll
        for (int in = 0; in < 8; ++in) {
            int col = n0 + wn * 64 + in * 8 + qc * 2;
            float* a = acc[im][in];
            if (MODE == 0) {
                float v0 = gate_act(a[0], actTanh);
                float v1 = gate_act(a[1], actTanh);
                float v2 = gate_act(a[2], actTanh);
                float v3 = gate_act(a[3], actTanh);
                *reinterpret_cast<__half2*>(C + (size_t)row * PPD + col) =
                    __floats2half2_rn(v0, v1);
                *reinterpret_cast<__half2*>(C + (size_t)(row + 8) * PPD + col) =
                    __floats2half2_rn(v2, v3);
            } else {
                const float2 x0 = *reinterpret_cast<const float2*>(resid + (size_t)row * DD + col);
                const float2 x1 = *reinterpret_cast<const float2*>(resid + (size_t)(row + 8) * DD + col);
                *reinterpret_cast<float2*>(outp + (size_t)row * DD + col) =
                    make_float2(a[0] + x0.x, a[1] + x0.y);
                *reinterpret_cast<float2*>(outp + (size_t)(row + 8) * DD + col) =
                    make_float2(a[2] + x1.x, a[3] + x1.y);
            }
        }
    }
}

// ---------------- sequential scan over S (prefetch depth 16) -----------------
__global__ void scan_kernel(const float* __restrict__ h0, float* __restrict__ hfin) {
    int p = blockIdx.x * blockDim.x + threadIdx.x;
    int b = blockIdx.y;
    if (p >= PD) return;
    float h = h0[(size_t)b * PD + p];
    size_t base = (size_t)b * SS * PPD + p;
    const __half* pi = g_gi + base;
    const __half* pf = g_gf + base;
    const __half* po = g_go + base;
    const __half* pc = g_gc + base;
    __half* pout = g_act + base;

    constexpr int PF = 16;
    __half bi[PF], bf[PF], bo[PF], bc[PF];
    #pragma unroll
    for (int j = 0; j < PF; ++j) {
        size_t o = (size_t)j * PPD;
        bi[j] = pi[o]; bf[j] = pf[o]; bo[j] = po[o]; bc[j] = pc[o];
    }
    #pragma unroll 16
    for (int s = 0; s < SS; ++s) {
        int slot = s & (PF - 1);
        float iv = __half2float(bi[slot]);
        float fv = __half2float(bf[slot]);
        float ov = __half2float(bo[slot]);
        float cv = __half2float(bc[slot]);
        int sn = s + PF;
        if (sn < SS) {
            size_t o = (size_t)sn * PPD;
            bi[slot] = pi[o]; bf[slot] = pf[o]; bo[slot] = po[o]; bc[slot] = pc[o];
        }
        h = fmaf(fv, h, iv * cv);                  // c already tanh'ed
        pout[(size_t)s * PPD] = __float2half_rn(ov * f_tanh(h));
    }
    if (hfin) hfin[(size_t)b * PD + p] = h;
}

// ---------------- launch -----------------------------------------------------
extern "C" void kernel_launch(void* const* d_in, const int* in_sizes, int n_in,
                              void* d_out, int out_size) {
    const float* x    = (const float*)d_in[0];
    const float* h0   = (const float*)d_in[1];
    const float* Wi   = (const float*)d_in[2];
    const float* Wf   = (const float*)d_in[3];
    const float* Wo   = (const float*)d_in[4];
    const float* Wc   = (const float*)d_in[5];
    const float* Wout = (const float*)d_in[6];
    const float* lnw  = (const float*)d_in[7];
    float* out = (float*)d_out;

    constexpr int SMEM_BYTES = 3 * 2 * 128 * 128;      // 98304 (3 stages, A+B)
    cudaFuncSetAttribute(gemm_fp16<0>, cudaFuncAttributeMaxDynamicSharedMemorySize, SMEM_BYTES);
    cudaFuncSetAttribute(gemm_fp16<1>, cudaFuncAttributeMaxDynamicSharedMemorySize, SMEM_BYTES);

    rmsnorm_kernel<<<BSD, 256>>>(x, lnw);
    convert_w_kernel<<<dim3(((size_t)PD * DD / 4 + 255) / 256, 4), 256>>>(Wi, Wf, Wo, Wc);
    pad_wout_kernel<<<((size_t)DD * PPD / 4 + 255) / 256, 256>>>(Wout);

    // gates: M=8192, N=PD (tiles to PPD), K=2048
    gemm_fp16<0><<<dim3(PPD / 128, BSD / 128, 4), 256, SMEM_BYTES>>>(
        nullptr, nullptr, PD, DD / 64, DD, DD);

    float* hfin = nullptr;
    if (out_size >= BSD * DD + BB * PD) hfin = out + (size_t)BSD * DD;
    scan_kernel<<<dim3((PD + 63) / 64, BB), 64>>>(h0, hfin);

    // out: M=8192, N=2048, K=PPD (act pad cols are zero)
    gemm_fp16<1><<<dim3(DD / 128, BSD / 128, 1), 256, SMEM_BYTES>>>(
        x, out, DD, PPD / 64, PPD, PPD);
}

// round 7
// speedup vs baseline: 2.5335x; 1.0191x over previous
#include <cuda_runtime.h>
#include <cuda_fp16.h>
#include <cstdint>
#include <cstddef>

// Shapes: B=4, S=2048, D=2048, P=int(2048*1.333)=2729
#define BSD 8192
#define DD  2048
#define PD  2729
#define PPD 2816          // P padded to multiple of 128 (BN) and 64 (BK)
#define BB  4
#define SS  2048

// ---------------- scratch (device globals) ----------------------------------
__device__ __align__(256) __half g_xn [(size_t)BSD * DD];
__device__ __align__(256) __half g_wi [(size_t)PD * DD];
__device__ __align__(256) __half g_wf [(size_t)PD * DD];
__device__ __align__(256) __half g_wo [(size_t)PD * DD];
__device__ __align__(256) __half g_wc [(size_t)PD * DD];
__device__ __align__(256) __half g_wout[(size_t)DD * PPD];   // padded cols zeroed
__device__ __align__(256) __half g_gi [(size_t)BSD * PPD];
__device__ __align__(256) __half g_gf [(size_t)BSD * PPD];
__device__ __align__(256) __half g_go [(size_t)BSD * PPD];
__device__ __align__(256) __half g_gc [(size_t)BSD * PPD];
__device__ __align__(256) __half g_act[(size_t)BSD * PPD];   // pad cols stay 0 (zero-init)

// ---------------- PTX helpers ------------------------------------------------
__device__ __forceinline__ uint32_t smem_u32(const void* p) {
    uint32_t a;
    asm("{ .reg .u64 t; cvta.to.shared.u64 t, %1; cvt.u32.u64 %0, t; }" : "=r"(a) : "l"(p));
    return a;
}
__device__ __forceinline__ void cp16(uint32_t dst, const void* src, int nbytes) {
    asm volatile("cp.async.cg.shared.global [%0], [%1], 16, %2;\n"
                 :: "r"(dst), "l"(src), "r"(nbytes));
}
__device__ __forceinline__ void cp_commit() { asm volatile("cp.async.commit_group;\n"); }
template<int N> __device__ __forceinline__ void cp_wait() {
    asm volatile("cp.async.wait_group %0;\n" :: "n"(N) : "memory");
}
__device__ __forceinline__ void ldsm4(uint32_t* r, uint32_t addr) {
    asm volatile("ldmatrix.sync.aligned.m8n8.x4.shared.b16 {%0,%1,%2,%3}, [%4];"
                 : "=r"(r[0]), "=r"(r[1]), "=r"(r[2]), "=r"(r[3]) : "r"(addr));
}
// m16n8k16 fp16 in, fp32 accum
__device__ __forceinline__ void mma16(float* c, const uint32_t* a, const uint32_t* b) {
    asm volatile(
        "mma.sync.aligned.m16n8k16.row.col.f32.f16.f16.f32 "
        "{%0,%1,%2,%3}, {%4,%5,%6,%7}, {%8,%9}, {%0,%1,%2,%3};\n"
        : "+f"(c[0]), "+f"(c[1]), "+f"(c[2]), "+f"(c[3])
        : "r"(a[0]), "r"(a[1]), "r"(a[2]), "r"(a[3]), "r"(b[0]), "r"(b[1]));
}

// ---------------- fast activations -------------------------------------------
__device__ __forceinline__ float f_ex2(float x) { float y; asm("ex2.approx.f32 %0, %1;" : "=f"(y) : "f"(x)); return y; }
__device__ __forceinline__ float f_rcp(float x) { float y; asm("rcp.approx.f32 %0, %1;" : "=f"(y) : "f"(x)); return y; }
__device__ __forceinline__ float f_tanh(float x) {
    x = fminf(fmaxf(x, -15.f), 15.f);
    float u = f_ex2(x * 2.885390082f);             // e^{2x}
    return (u - 1.f) * f_rcp(u + 1.f);
}
__device__ __forceinline__ float f_sig(float x) {
    float v = f_ex2(-x * 1.442695041f);
    return f_rcp(1.f + v);
}
__device__ __forceinline__ float gate_act(float z, bool tanhOnly) {
    if (tanhOnly) return f_tanh(z);
    float t = 15.f * f_tanh(z * (1.f / 15.f));     // soft cap
    return f_sig(t);
}

// ---------------- rmsnorm -> fp16 --------------------------------------------
__global__ void rmsnorm_kernel(const float* __restrict__ x, const float* __restrict__ w) {
    int row = blockIdx.x;
    int t = threadIdx.x;
    const float4* xr = reinterpret_cast<const float4*>(x + (size_t)row * DD);
    float4 v0 = xr[t], v1 = xr[t + 256];
    float ss = v0.x*v0.x + v0.y*v0.y + v0.z*v0.z + v0.w*v0.w
             + v1.x*v1.x + v1.y*v1.y + v1.z*v1.z + v1.w*v1.w;
    #pragma unroll
    for (int o = 16; o > 0; o >>= 1) ss += __shfl_xor_sync(0xffffffffu, ss, o);
    __shared__ float red[8];
    if ((t & 31) == 0) red[t >> 5] = ss;
    __syncthreads();
    float tot = red[0]+red[1]+red[2]+red[3]+red[4]+red[5]+red[6]+red[7];
    float r = rsqrtf(tot * (1.0f / DD) + 1e-6f);
    const float4* wr = reinterpret_cast<const float4*>(w);
    float4 w0 = wr[t], w1 = wr[t + 256];
    __half2* dst = reinterpret_cast<__half2*>(g_xn + (size_t)row * DD);
    dst[t*2  ]       = __floats2half2_rn(v0.x*r*w0.x, v0.y*r*w0.y);
    dst[t*2+1]       = __floats2half2_rn(v0.z*r*w0.z, v0.w*r*w0.w);
    dst[(t+256)*2  ] = __floats2half2_rn(v1.x*r*w1.x, v1.y*r*w1.y);
    dst[(t+256)*2+1] = __floats2half2_rn(v1.z*r*w1.z, v1.w*r*w1.w);
}

// ---------------- weight conversion (vectorized) -----------------------------
__global__ void convert_w_kernel(const float* __restrict__ W0, const float* __restrict__ W1,
                                 const float* __restrict__ W2, const float* __restrict__ W3) {
    size_t i4 = (size_t)blockIdx.x * blockDim.x + threadIdx.x;
    if (i4 >= (size_t)PD * DD / 4) return;
    int z = blockIdx.y;
    const float* src = (z == 0) ? W0 : (z == 1) ? W1 : (z == 2) ? W2 : W3;
    __half* dst = (z == 0) ? g_wi : (z == 1) ? g_wf : (z == 2) ? g_wo : g_wc;
    float4 v = reinterpret_cast<const float4*>(src)[i4];
    __half2 h0 = __floats2half2_rn(v.x, v.y);
    __half2 h1 = __floats2half2_rn(v.z, v.w);
    *reinterpret_cast<uint2*>(dst + i4 * 4) =
        make_uint2(*reinterpret_cast<uint32_t*>(&h0), *reinterpret_cast<uint32_t*>(&h1));
}
__global__ void pad_wout_kernel(const float* __restrict__ wout) {
    size_t i4 = (size_t)blockIdx.x * blockDim.x + threadIdx.x;
    if (i4 >= (size_t)DD * PPD / 4) return;
    int d = (int)(i4 / (PPD / 4));
    int p = (int)(i4 % (PPD / 4)) * 4;
    const float* src = wout + (size_t)d * PD + p;
    float a0 = (p     < PD) ? src[0] : 0.f;
    float a1 = (p + 1 < PD) ? src[1] : 0.f;
    float a2 = (p + 2 < PD) ? src[2] : 0.f;
    float a3 = (p + 3 < PD) ? src[3] : 0.f;
    __half2 h0 = __floats2half2_rn(a0, a1);
    __half2 h1 = __floats2half2_rn(a2, a3);
    *reinterpret_cast<uint2*>(g_wout + i4 * 4) =
        make_uint2(*reinterpret_cast<uint32_t*>(&h0), *reinterpret_cast<uint32_t*>(&h1));
}

// ---------------- fp16 TN GEMM: C[M,N] = A[M,K] * B[N,K]^T -------------------
// XOR-swizzled smem (row = 128B): chunk c of row r at byte r*128 + ((c^(r&7))<<4).
// fill() invariants: c = tid&7 and r&7 = (tid>>3)&7 are constant across the 4
// per-thread chunks (row step 32 = 0 mod 8), so ONE swizzled smem offset (+i*4096)
// and ONE running global pointer per matrix (+BK halves/kt, +32 rows per chunk)
// cover all 8 cp.async issues.
template<int MODE>
__global__ __launch_bounds__(256, 2)
void gemm_fp16(const float* __restrict__ resid, float* __restrict__ outp,
               int Nreal, int KT, int lda, int ldb)
{
    constexpr int BM = 128, BN = 128, BK = 64;
    constexpr int TILE_B = BM * 128;        // 16384 bytes per tile (A or B)
    constexpr int STG = 2 * TILE_B;         // 32768 bytes per stage
    extern __shared__ char dsm[];

    const int tid  = threadIdx.x;
    const int lane = tid & 31;
    const int wid  = tid >> 5;
    const int wm   = wid & 3;               // 4 warps along M (32 rows)
    const int wn   = wid >> 2;              // 2 warps along N (64 cols)
    const int m0   = blockIdx.y * BM;
    const int n0   = blockIdx.x * BN;

    const __half* A;
    const __half* Bw;
    __half* C = nullptr;
    bool actTanh = false;
    if (MODE == 0) {
        A = g_xn;
        int z = blockIdx.z;
        Bw = (z == 0) ? g_wi : (z == 1) ? g_wf : (z == 2) ? g_wo : g_wc;
        C  = (z == 0) ? g_gi : (z == 1) ? g_gf : (z == 2) ? g_go : g_gc;
        actTanh = (z == 3);
    } else {
        A = g_act; Bw = g_wout;
    }

    const uint32_t sbase = smem_u32(dsm);

    // ---- fill() invariants ---------------------------------------------------
    const int tr = tid >> 3;                 // base row 0..31
    const int tc = tid & 7;                  // 16B chunk, constant
    const uint32_t offS = (uint32_t)(tr * 128 + ((tc ^ (tr & 7)) << 4));  // smem off
    // running global pointers (advance BK halves per kt)
    const __half* pA = A + (size_t)(m0 + tr) * lda + tc * 8;
    // B row clamping: row(i) = n0 + tr + i*32; i=0 always < Nreal (n0<=2688, tr<=31)
    int nb[4];
    size_t dB[4];
    #pragma unroll
    for (int i = 0; i < 4; ++i) {
        int r = n0 + tr + i * 32;
        int ok = (MODE == 1) || (r < Nreal);
        nb[i] = ok ? 16 : 0;
        dB[i] = (size_t)(ok ? (size_t)i * 32 * ldb : 0);
    }
    const __half* pB = Bw + (size_t)(n0 + tr) * ldb + tc * 8;

    auto fill = [&](uint32_t stg) {
        uint32_t ab = stg + offS;
        #pragma unroll
        for (int i = 0; i < 4; ++i)
            cp16(ab + i * 4096, pA + (size_t)i * 32 * lda, 16);
        uint32_t bb = ab + TILE_B;
        #pragma unroll
        for (int i = 0; i < 4; ++i)
            cp16(bb + i * 4096, pB + dB[i], nb[i]);
        cp_commit();
        pA += BK;
        pB += BK;
    };

    float acc[2][8][4];
    #pragma unroll
    for (int im = 0; im < 2; ++im)
        #pragma unroll
        for (int in = 0; in < 8; ++in)
            #pragma unroll
            for (int j = 0; j < 4; ++j) acc[im][in][j] = 0.0f;

    // ---- precomputed ldmatrix addresses --------------------------------------
    const int l7 = lane & 7, l6 = lane & 6, l1 = lane & 1;
    const int a_row = ((lane >> 3) & 1) * 8 + l7;
    const int a_ch  = (lane >> 4);                   // 0/1
    const int b_row = ((lane >> 4) & 1) * 8 + l7;
    const int b_ch  = (lane >> 3) & 1;
    uint32_t baseA[2], baseB[4], dks[4];
    #pragma unroll
    for (int im = 0; im < 2; ++im)
        baseA[im] = (uint32_t)((wm * 32 + im * 16 + a_row) * 128 + ((a_ch ^ l1) << 4));
    #pragma unroll
    for (int ip = 0; ip < 4; ++ip)
        baseB[ip] = (uint32_t)(TILE_B + (wn * 64 + ip * 16 + b_row) * 128 + ((b_ch ^ l1) << 4));
    #pragma unroll
    for (int ks = 0; ks < 4; ++ks)
        dks[ks] = (uint32_t)(((2 * ks) ^ l6) << 4);

    const uint32_t stg0 = sbase, stg1 = sbase + STG, stg2 = sbase + 2 * STG;

    fill(stg0);
    fill(stg1);
    cp_wait<1>();
    __syncthreads();

    int s = 0, sf = 2;          // current stage id, next-fill stage id
    for (int kt = 0; kt < KT; ++kt) {
        if (kt + 2 < KT) {
            fill(sf == 0 ? stg0 : sf == 1 ? stg1 : stg2);
            if (++sf == 3) sf = 0;
        } else cp_commit();

        const uint32_t stA = (s == 0) ? stg0 : (s == 1) ? stg1 : stg2;

        #pragma unroll
        for (int ks = 0; ks < 4; ++ks) {
            const uint32_t d = dks[ks];
            uint32_t ra[2][4];
            #pragma unroll
            for (int im = 0; im < 2; ++im)
                ldsm4(ra[im], stA + baseA[im] + d);
            #pragma unroll
            for (int ip = 0; ip < 4; ++ip) {
                uint32_t r4[4];
                ldsm4(r4, stA + baseB[ip] + d);
                #pragma unroll
                for (int im = 0; im < 2; ++im) {
                    mma16(acc[im][2*ip    ], ra[im], r4);
                    mma16(acc[im][2*ip + 1], ra[im], r4 + 2);
                }
            }
        }
        cp_wait<1>();
        __syncthreads();
        if (++s == 3) s = 0;
    }

    // ---- epilogue (branch-free; gate-plane pad cols are never read) ----------
    const int qr = lane >> 2;        // 0..7
    const int qc = lane & 3;         // 0..3
    #pragma unroll
    for (int im = 0; im < 2; ++im) {
        int row = m0 + wm * 32 + im * 16 + qr;
        #pragma unroll
        for (int in = 0; in < 8; ++in) {
            int col = n0 + wn * 64 + in * 8 + qc * 2;
            float* a = acc[im][in];
            if (MODE == 0) {
                float v0 = gate_act(a[0], actTanh);
                float v1 = gate_act(a[1], actTanh);
                float v2 = gate_act(a[2], actTanh);
                float v3 = gate_act(a[3], actTanh);
                *reinterpret_cast<__half2*>(C + (size_t)row * PPD + col) =
                    __floats2half2_rn(v0, v1);
                *reinterpret_cast<__half2*>(C + (size_t)(row + 8) * PPD + col) =
                    __floats2half2_rn(v2, v3);
            } else {
                const float2 x0 = *reinterpret_cast<const float2*>(resid + (size_t)row * DD + col);
                const float2 x1 = *reinterpret_cast<const float2*>(resid + (size_t)(row + 8) * DD + col);
                *reinterpret_cast<float2*>(outp + (size_t)row * DD + col) =
                    make_float2(a[0] + x0.x, a[1] + x0.y);
                *reinterpret_cast<float2*>(outp + (size_t)(row + 8) * DD + col) =
                    make_float2(a[2] + x1.x, a[3] + x1.y);
            }
        }
    }
}

// ---------------- sequential scan over S (prefetch depth 16) -----------------
__global__ void scan_kernel(const float* __restrict__ h0, float* __restrict__ hfin) {
    int p = blockIdx.x * blockDim.x + threadIdx.x;
    int b = blockIdx.y;
    if (p >= PD) return;
    float h = h0[(size_t)b * PD + p];
    size_t base = (size_t)b * SS * PPD + p;
    const __half* pi = g_gi + base;
    const __half* pf = g_gf + base;
    const __half* po = g_go + base;
    const __half* pc = g_gc + base;
    __half* pout = g_act + base;

    constexpr int PF = 16;
    __half bi[PF], bf[PF], bo[PF], bc[PF];
    #pragma unroll
    for (int j = 0; j < PF; ++j) {
        size_t o = (size_t)j * PPD;
        bi[j] = pi[o]; bf[j] = pf[o]; bo[j] = po[o]; bc[j] = pc[o];
    }
    #pragma unroll 16
    for (int s = 0; s < SS; ++s) {
        int slot = s & (PF - 1);
        float iv = __half2float(bi[slot]);
        float fv = __half2float(bf[slot]);
        float ov = __half2float(bo[slot]);
        float cv = __half2float(bc[slot]);
        int sn = s + PF;
        if (sn < SS) {
            size_t o = (size_t)sn * PPD;
            bi[slot] = pi[o]; bf[slot] = pf[o]; bo[slot] = po[o]; bc[slot] = pc[o];
        }
        h = fmaf(fv, h, iv * cv);                  // c already tanh'ed
        pout[(size_t)s * PPD] = __float2half_rn(ov * f_tanh(h));
    }
    if (hfin) hfin[(size_t)b * PD + p] = h;
}

// ---------------- launch -----------------------------------------------------
extern "C" void kernel_launch(void* const* d_in, const int* in_sizes, int n_in,
                              void* d_out, int out_size) {
    const float* x    = (const float*)d_in[0];
    const float* h0   = (const float*)d_in[1];
    const float* Wi   = (const float*)d_in[2];
    const float* Wf   = (const float*)d_in[3];
    const float* Wo   = (const float*)d_in[4];
    const float* Wc   = (const float*)d_in[5];
    const float* Wout = (const float*)d_in[6];
    const float* lnw  = (const float*)d_in[7];
    float* out = (float*)d_out;

    constexpr int SMEM_BYTES = 3 * 2 * 128 * 128;      // 98304 (3 stages, A+B)
    cudaFuncSetAttribute(gemm_fp16<0>, cudaFuncAttributeMaxDynamicSharedMemorySize, SMEM_BYTES);
    cudaFuncSetAttribute(gemm_fp16<1>, cudaFuncAttributeMaxDynamicSharedMemorySize, SMEM_BYTES);

    rmsnorm_kernel<<<BSD, 256>>>(x, lnw);
    convert_w_kernel<<<dim3(((size_t)PD * DD / 4 + 255) / 256, 4), 256>>>(Wi, Wf, Wo, Wc);
    pad_wout_kernel<<<((size_t)DD * PPD / 4 + 255) / 256, 256>>>(Wout);

    // gates: M=8192, N=PD (tiles to PPD), K=2048
    gemm_fp16<0><<<dim3(PPD / 128, BSD / 128, 4), 256, SMEM_BYTES>>>(
        nullptr, nullptr, PD, DD / 64, DD, DD);

    float* hfin = nullptr;
    if (out_size >= BSD * DD + BB * PD) hfin = out + (size_t)BSD * DD;
    scan_kernel<<<dim3((PD + 63) / 64, BB), 64>>>(h0, hfin);

    // out: M=8192, N=2048, K=PPD (act pad cols are zero)
    gemm_fp16<1><<<dim3(DD / 128, BSD / 128, 1), 256, SMEM_BYTES>>>(
        x, out, DD, PPD / 64, PPD, PPD);
}